// round 16
// baseline (speedup 1.0000x reference)
#include <cuda_runtime.h>
#include <cstdint>

// SpatialCorrelationSampler via warp-level mma.sync fp16 m16n8k16 (fp32 acc).
// Round 16: VERTICAL 8w x 16h tile. Halo 16w x 24h -> N=384 for M=128:
// B amplification 3x (L2 traffic 268 MB vs 336) AND band sharing: each m16
// tile = 2 image rows -> 10 q-rows x 2 n8 = 20 frags/warp (MMA total 0.74x).
// 8 warps, ~110 regs -> 2 blocks/SM. 2-stage cp.async ring (r9-validated
// pattern). Two-pass banded-D epilogue fits inside the dead stage area.

namespace {

constexpr int C = 256, H = 128, W = 128, PATCH = 9, PAD = 4;
constexpr int HW = H * W;
constexpr int TW = 8, TH = 16;                    // tile 8 wide x 16 tall
constexpr int HALO_W = 16, HALO_H = 24;           // halo; q = hy*16 + wx
constexpr int CCH = 16, NCHUNK = C / CCH;         // 16 chunks, 1 k16 each
constexpr int CHBYTES = CCH * HW * 4;

constexpr int A_ST = 132;                         // floats (128 + 4)
constexpr int B_ST = 388;                         // floats (384 + 4)
constexpr int A_STAGE = CCH * A_ST * 4;           // 8448
constexpr int B_STAGE = CCH * B_ST * 4;           // 24832
constexpr int STAGE  = A_STAGE + B_STAGE;         // 33280
constexpr int STAGES = 2;
constexpr int D_ST = 162;                         // banded D (10*16=160 + 2)
constexpr int DYN_BYTES = STAGES * STAGE;         // 66560 > 64*162*4 = 41472

constexpr int SLOTS = 8;    // (512 A + 1536 B) float4 per chunk / 256 thr

// ---------------- PTX wrappers (baseline ISA) ------------------------------
__device__ __forceinline__ void cp16(uint32_t dst, const void* src, uint32_t sz) {
    asm volatile("cp.async.cg.shared.global [%0], [%1], 16, %2;"
                 :: "r"(dst), "l"(src), "r"(sz));
}
__device__ __forceinline__ void cp_commit() {
    asm volatile("cp.async.commit_group;" ::: "memory");
}
__device__ __forceinline__ void cp_wait0() {
    asm volatile("cp.async.wait_group 0;" ::: "memory");
}
// pack two fp32 -> fp16x2; v_even in LOWER half (r12-validated)
__device__ __forceinline__ uint32_t pkh(float v_even, float v_odd) {
    uint32_t r;
    asm("cvt.rn.f16x2.f32 %0, %1, %2;" : "=r"(r) : "f"(v_odd), "f"(v_even));
    return r;
}
__device__ __forceinline__ void mma_fp16(float* d, const uint32_t* a,
                                         uint32_t b0, uint32_t b1) {
    asm volatile("mma.sync.aligned.m16n8k16.row.col.f32.f16.f16.f32 "
                 "{%0,%1,%2,%3}, {%4,%5,%6,%7}, {%8,%9}, {%0,%1,%2,%3};"
                 : "+f"(d[0]), "+f"(d[1]), "+f"(d[2]), "+f"(d[3])
                 : "r"(a[0]), "r"(a[1]), "r"(a[2]), "r"(a[3]), "r"(b0), "r"(b1));
}

__global__ __launch_bounds__(256, 2)
void corr_v_kernel(const float* __restrict__ in1,
                   const float* __restrict__ in2,
                   float* __restrict__ out) {
    extern __shared__ char sm[];
    const uint32_t smb = (uint32_t)__cvta_generic_to_shared(sm);

    const int tid  = threadIdx.x;
    const int warp = tid >> 5;
    const int lane = tid & 31;
    const int b  = blockIdx.z;
    const int w0 = blockIdx.x * TW;
    const int h0 = blockIdx.y * TH;

    // ------------- cp.async slot precompute (8 x 16B per thread) -----------
    // slots 0..511: A [k(16)][p(128)], p = hy*8+wx; 512..2047: B [k(16)][q(384)]
    uint32_t smoff[SLOTS], gb[SLOTS], sz[SLOTS];
#pragma unroll
    for (int i = 0; i < SLOTS; ++i) {
        int s = tid + i * 256;
        if (s < 512) {                        // A (i = 0,1)
            int kk = s >> 5, j = s & 31;      // j = p/4
            int hy = j >> 1, wx = (j & 1) * 4;
            smoff[i] = (uint32_t)((kk * A_ST + j * 4) * 4);
            gb[i] = (uint32_t)((((b * C + kk) * H + h0 + hy) * W + w0 + wx) * 4);
            sz[i] = 16;
        } else {                              // B (i = 2..7)
            int u = s - 512;
            int kk = u / 96, r = u % 96;      // r = q/4
            int hy = r >> 2;                  // 0..23
            int gy = h0 + hy - PAD;
            int gx = w0 + (r & 3) * 4 - PAD;  // 16B aligned: all-in or all-out
            bool ok = (gy >= 0 && gy < H && gx >= 0 && gx + 4 <= W);
            smoff[i] = (uint32_t)(A_STAGE + (kk * B_ST + r * 4) * 4);
            gb[i] = ok ? (uint32_t)((((b * C + kk) * H + gy) * W + gx) * 4) : 0u;
            sz[i] = ok ? 16u : 0u;
        }
    }

    auto issue = [&](int ch) {
        uint32_t sbase = smb + (uint32_t)((ch & 1) * STAGE);
        size_t coff = (size_t)ch * CHBYTES;
#pragma unroll
        for (int i = 0; i < SLOTS; ++i) {
            const char* base = (i < 2) ? (const char*)in1 : (const char*)in2;
            cp16(sbase + smoff[i], base + coff + gb[i], sz[i]);
        }
        cp_commit();
    };

    issue(0);

    // ------------- MMA roles: warp mt owns m16 tile = image rows {2mt,2mt+1}
    const int g = lane >> 2, t = lane & 3;
    const int mt = warp;                   // 0..7; px p = mt*16 + (0..15)
    // band: halo rows 2mt..2mt+9 (10 rows x 2 n8 tiles = 20 frags)

    float acc[20][4];                      // j = lr*2 + nhalf
#pragma unroll
    for (int j = 0; j < 20; ++j)
#pragma unroll
        for (int q = 0; q < 4; ++q) acc[j][q] = 0.f;

#pragma unroll 1
    for (int k = 0; k < NCHUNK; ++k) {
        cp_wait0();        // pending = {k} only -> group k complete
        __syncthreads();   // stage k&1 visible; stage (k+1)&1 fully read (k-1)

        if (k + 1 < NCHUNK) issue(k + 1);

        const float* A  = (const float*)(sm + (k & 1) * STAGE);
        const float* Bs = (const float*)(sm + (k & 1) * STAGE + A_STAGE);

        // A fragment m16 x k16 (r12-validated map)
        const int p = mt * 16 + g;
        uint32_t a[4];
        a[0] = pkh(A[(2 * t) * A_ST + p],         A[(2 * t + 1) * A_ST + p]);
        a[1] = pkh(A[(2 * t) * A_ST + p + 8],     A[(2 * t + 1) * A_ST + p + 8]);
        a[2] = pkh(A[(2 * t + 8) * A_ST + p],     A[(2 * t + 9) * A_ST + p]);
        a[3] = pkh(A[(2 * t + 8) * A_ST + p + 8], A[(2 * t + 9) * A_ST + p + 8]);

#pragma unroll
        for (int j = 0; j < 20; ++j) {
            const int q = (2 * mt + (j >> 1)) * HALO_W + (j & 1) * 8 + g;
            uint32_t b0 = pkh(Bs[(2 * t) * B_ST + q],
                              Bs[(2 * t + 1) * B_ST + q]);
            uint32_t b1 = pkh(Bs[(2 * t + 8) * B_ST + q],
                              Bs[(2 * t + 9) * B_ST + q]);
            mma_fp16(acc[j], a, b0, b1);
        }
    }

    // ------------- epilogue: two passes over h-halves (banded D) -----------
    __syncthreads();            // all MMA smem reads done; stages are dead
    float* D = (float*)sm;      // [px_local 0..63][lr*16 + wx] stride 162

    const int c2 = t * 2;
#pragma unroll
    for (int pass = 0; pass < 2; ++pass) {
        if ((mt >> 2) == pass) {
            const int pl = (mt & 3) * 16 + g;
#pragma unroll
            for (int j = 0; j < 20; ++j) {
                const int q = (j >> 1) * 16 + (j & 1) * 8 + c2;
                *(float2*)&D[pl * D_ST + q]       = make_float2(acc[j][0], acc[j][1]);
                *(float2*)&D[(pl + 8) * D_ST + q] = make_float2(acc[j][2], acc[j][3]);
            }
        }
        __syncthreads();

        // gather: 81 planes x 8 pixel-rows (hp = pass*8 + hpl) of 8 floats
        for (int i = tid; i < 8 * 81; i += 256) {
            const int hpl = i & 7, dd = i >> 3;     // dd = dy*9+dx
            const int dy = dd / 9, dx = dd % 9;
            const int hp = pass * 8 + hpl;
            const int lr = (hp & 1) + dy;           // band-local q-row
            float v[8];
#pragma unroll
            for (int wp = 0; wp < 8; ++wp)
                v[wp] = D[(hpl * 8 + wp) * D_ST + lr * 16 + wp + dx];
            float* op = out + (((size_t)b * (PATCH * PATCH) + dd) * H
                               + (h0 + hp)) * W + w0;
            *(float4*)(op)     = make_float4(v[0], v[1], v[2], v[3]);
            *(float4*)(op + 4) = make_float4(v[4], v[5], v[6], v[7]);
        }
        __syncthreads();   // reads done before next pass overwrites D
    }
}

}  // namespace

extern "C" void kernel_launch(void* const* d_in, const int* in_sizes, int n_in,
                              void* d_out, int out_size) {
    const float* in1 = (const float*)d_in[0];
    const float* in2 = (const float*)d_in[1];
    float* out = (float*)d_out;

    cudaFuncSetAttribute(corr_v_kernel,
                         cudaFuncAttributeMaxDynamicSharedMemorySize,
                         DYN_BYTES);

    int B = in_sizes[0] / (C * H * W);              // 4
    dim3 grid(W / TW, H / TH, B);                   // (16, 8, 4) = 512
    corr_v_kernel<<<grid, 256, DYN_BYTES>>>(in1, in2, out);
}